// round 1
// baseline (speedup 1.0000x reference)
#include <cuda_runtime.h>
#include <cuda_bf16.h>
#include <math.h>

// Problem constants
#define HIDDEN   1280
#define NUM_H    16
#define NUM_KVH  4
#define HDIM     80
#define Q_SIZE   1280          // 16*80
#define KV_SIZE  320           // 4*80
#define QKV_OUT  1920
#define BATCH    4
#define SEQ      2048
#define ROWS     (BATCH*SEQ)   // 8192

// Scratch (device globals — allocation-free rule)
__device__ float g_qkv[(size_t)ROWS * QKV_OUT];    // [8192,1920]
__device__ float g_attn[(size_t)ROWS * Q_SIZE];    // [8192,1280]

// ---------------------------------------------------------------------------
// GEMM:  C[M,N] = A[M,K] * B[N,K]^T + bias[N]   (both row-major, K contiguous)
// 128x128 tile, BK=16, 256 threads, 8x8 microtile.
// Requires M%128==0, N%128==0, K%16==0 (holds for all our shapes).
// ---------------------------------------------------------------------------
__global__ __launch_bounds__(256)
void sgemm_nt_bias(const float* __restrict__ A, const float* __restrict__ B,
                   const float* __restrict__ bias, float* __restrict__ C,
                   int M, int N, int K)
{
    const int BM = 128, BN = 128, BK = 16;
    __shared__ float As[BK][BM];
    __shared__ float Bs[BK][BN];

    int tid = threadIdx.x;
    int tx = tid & 15;          // 0..15 -> N direction
    int ty = tid >> 4;          // 0..15 -> M direction
    int row0 = blockIdx.y * BM;
    int col0 = blockIdx.x * BN;

    int lr = tid >> 2;          // 0..63
    int lc = (tid & 3) << 2;    // 0,4,8,12

    float acc[8][8];
#pragma unroll
    for (int i = 0; i < 8; i++)
#pragma unroll
        for (int j = 0; j < 8; j++) acc[i][j] = 0.f;

    for (int kt = 0; kt < K; kt += BK) {
#pragma unroll
        for (int h = 0; h < 2; h++) {
            int r = lr + h * 64;
            float4 v = *(const float4*)&A[(size_t)(row0 + r) * K + kt + lc];
            As[lc + 0][r] = v.x; As[lc + 1][r] = v.y;
            As[lc + 2][r] = v.z; As[lc + 3][r] = v.w;
        }
#pragma unroll
        for (int h = 0; h < 2; h++) {
            int r = lr + h * 64;
            float4 v = *(const float4*)&B[(size_t)(col0 + r) * K + kt + lc];
            Bs[lc + 0][r] = v.x; Bs[lc + 1][r] = v.y;
            Bs[lc + 2][r] = v.z; Bs[lc + 3][r] = v.w;
        }
        __syncthreads();

#pragma unroll
        for (int k = 0; k < BK; k++) {
            float a[8], b[8];
            *(float4*)&a[0] = *(const float4*)&As[k][ty * 8];
            *(float4*)&a[4] = *(const float4*)&As[k][ty * 8 + 4];
            *(float4*)&b[0] = *(const float4*)&Bs[k][tx * 8];
            *(float4*)&b[4] = *(const float4*)&Bs[k][tx * 8 + 4];
#pragma unroll
            for (int i = 0; i < 8; i++)
#pragma unroll
                for (int j = 0; j < 8; j++)
                    acc[i][j] += a[i] * b[j];
        }
        __syncthreads();
    }

#pragma unroll
    for (int i = 0; i < 8; i++) {
        size_t r = row0 + ty * 8 + i;
#pragma unroll
        for (int j = 0; j < 8; j++) {
            int c = col0 + tx * 8 + j;
            C[r * N + c] = acc[i][j] + bias[c];
        }
    }
}

// ---------------------------------------------------------------------------
// Flash attention, fp32, full (non-causal) softmax.
// grid = (SEQ/64, NUM_H, BATCH), block = 256 threads.
// Thread (tx=tid%16, ty=tid/16): owns 4 q-rows (ty*4..), 4 score cols (tx*4..),
// and 5 output dims (tx*5..).
// ---------------------------------------------------------------------------
#define BQ   64
#define BKV  64
#define QLD  84     // padded row stride for Qs / KVs (keeps float4 alignment)

__global__ __launch_bounds__(256)
void attn_kernel(const float* __restrict__ qkv, const float* __restrict__ scaling,
                 float* __restrict__ attn_out)
{
    extern __shared__ float sm[];
    float* Qs  = sm;                    // [64][QLD]
    float* KVs = Qs + BQ * QLD;         // [64][QLD]
    float* Ps  = KVs + BKV * QLD;       // [64][64]
    __shared__ float sscale[HDIM];

    int tid = threadIdx.x;
    int tx = tid & 15;
    int ty = tid >> 4;
    int q0 = blockIdx.x * BQ;
    int h  = blockIdx.y;
    int b  = blockIdx.z;
    int kvh = h >> 2;

    // learned scale: (log2(e)/sqrt(d)) * softplus(scaling)
    if (tid < HDIM) {
        float x = scaling[tid];
        float sp = (x > 20.f) ? x : log1pf(__expf(x));
        sscale[tid] = 1.442695041f * rsqrtf((float)HDIM) * sp;
    }
    __syncthreads();

    // Load scaled Q tile into smem
    for (int idx = tid * 4; idx < BQ * HDIM; idx += 256 * 4) {
        int r = idx / HDIM;
        int d = idx % HDIM;
        const float* src = &qkv[(size_t)(b * SEQ + q0 + r) * QKV_OUT + h * HDIM + d];
        float4 v = *(const float4*)src;
        v.x *= sscale[d + 0]; v.y *= sscale[d + 1];
        v.z *= sscale[d + 2]; v.w *= sscale[d + 3];
        *(float4*)&Qs[r * QLD + d] = v;
    }

    float m_i[4], l_i[4], o[4][5];
#pragma unroll
    for (int i = 0; i < 4; i++) {
        m_i[i] = -1e30f; l_i[i] = 0.f;
#pragma unroll
        for (int j = 0; j < 5; j++) o[i][j] = 0.f;
    }

    for (int k0 = 0; k0 < SEQ; k0 += BKV) {
        // load K tile (sync first: previous iter's V reads must be done)
        __syncthreads();
        for (int idx = tid * 4; idx < BKV * HDIM; idx += 256 * 4) {
            int r = idx / HDIM;
            int d = idx % HDIM;
            const float* src = &qkv[(size_t)(b * SEQ + k0 + r) * QKV_OUT
                                    + Q_SIZE + kvh * HDIM + d];
            *(float4*)&KVs[r * QLD + d] = *(const float4*)src;
        }
        __syncthreads();

        // scores s[4][4] = Q(4 rows) . K(4 cols)
        float s[4][4];
#pragma unroll
        for (int i = 0; i < 4; i++)
#pragma unroll
            for (int j = 0; j < 4; j++) s[i][j] = 0.f;

        for (int d = 0; d < HDIM; d += 4) {
            float4 qv[4], kv[4];
#pragma unroll
            for (int i = 0; i < 4; i++)
                qv[i] = *(const float4*)&Qs[(ty * 4 + i) * QLD + d];
#pragma unroll
            for (int j = 0; j < 4; j++)
                kv[j] = *(const float4*)&KVs[(tx * 4 + j) * QLD + d];
#pragma unroll
            for (int i = 0; i < 4; i++)
#pragma unroll
                for (int j = 0; j < 4; j++) {
                    s[i][j] += qv[i].x * kv[j].x;
                    s[i][j] += qv[i].y * kv[j].y;
                    s[i][j] += qv[i].z * kv[j].z;
                    s[i][j] += qv[i].w * kv[j].w;
                }
        }

        // online softmax update (row reductions across the 16 tx lanes)
#pragma unroll
        for (int i = 0; i < 4; i++) {
            float tm = fmaxf(fmaxf(s[i][0], s[i][1]), fmaxf(s[i][2], s[i][3]));
#pragma unroll
            for (int off = 8; off >= 1; off >>= 1)
                tm = fmaxf(tm, __shfl_xor_sync(0xffffffffu, tm, off, 16));
            float m_new = fmaxf(m_i[i], tm);
            float alpha = __expf(m_i[i] - m_new);
            m_i[i] = m_new;

            float rs = 0.f;
#pragma unroll
            for (int j = 0; j < 4; j++) {
                float p = __expf(s[i][j] - m_new);
                Ps[(ty * 4 + i) * BKV + tx * 4 + j] = p;
                rs += p;
            }
#pragma unroll
            for (int off = 8; off >= 1; off >>= 1)
                rs += __shfl_xor_sync(0xffffffffu, rs, off, 16);
            l_i[i] = l_i[i] * alpha + rs;
#pragma unroll
            for (int j = 0; j < 5; j++) o[i][j] *= alpha;
        }
        __syncthreads();   // Ps written, everyone done reading K

        // load V tile into same smem
        for (int idx = tid * 4; idx < BKV * HDIM; idx += 256 * 4) {
            int r = idx / HDIM;
            int d = idx % HDIM;
            const float* src = &qkv[(size_t)(b * SEQ + k0 + r) * QKV_OUT
                                    + Q_SIZE + KV_SIZE + kvh * HDIM + d];
            *(float4*)&KVs[r * QLD + d] = *(const float4*)src;
        }
        __syncthreads();

        // O += P . V   (this thread: 4 rows x 5 dims)
        for (int kc = 0; kc < BKV; kc++) {
            float vv[5];
#pragma unroll
            for (int j = 0; j < 5; j++)
                vv[j] = KVs[kc * QLD + tx * 5 + j];
#pragma unroll
            for (int i = 0; i < 4; i++) {
                float p = Ps[(ty * 4 + i) * BKV + kc];
#pragma unroll
                for (int j = 0; j < 5; j++)
                    o[i][j] += p * vv[j];
            }
        }
    }

    // normalize and write out: attn_out[(b*SEQ+q), h*80 + d]
#pragma unroll
    for (int i = 0; i < 4; i++) {
        float inv = 1.f / l_i[i];
        size_t row = (size_t)(b * SEQ + q0 + ty * 4 + i);
#pragma unroll
        for (int j = 0; j < 5; j++)
            attn_out[row * Q_SIZE + h * HDIM + tx * 5 + j] = o[i][j] * inv;
    }
}

// ---------------------------------------------------------------------------
extern "C" void kernel_launch(void* const* d_in, const int* in_sizes, int n_in,
                              void* d_out, int out_size)
{
    const float* hidden  = (const float*)d_in[0];   // [4,2048,1280]
    const float* scaling = (const float*)d_in[1];   // [80]
    const float* qkv_w   = (const float*)d_in[2];   // [1920,1280]
    const float* qkv_b   = (const float*)d_in[3];   // [1920]
    const float* o_w     = (const float*)d_in[4];   // [1280,1280]
    const float* o_b     = (const float*)d_in[5];   // [1280]
    float* out = (float*)d_out;                     // [4,2048,1280]

    float* qkv_buf = nullptr;
    float* attn_buf = nullptr;
    cudaGetSymbolAddress((void**)&qkv_buf, g_qkv);
    cudaGetSymbolAddress((void**)&attn_buf, g_attn);

    // attention smem: Qs + KVs (64x84) + Ps (64x64)
    const int attn_smem = (BQ * QLD + BKV * QLD + BQ * BKV) * (int)sizeof(float);
    static bool attr_set = false;
    if (!attr_set) {
        cudaFuncSetAttribute(attn_kernel,
                             cudaFuncAttributeMaxDynamicSharedMemorySize, attn_smem);
        attr_set = true;
    }

    // 1) QKV projection: [8192,1280] x [1920,1280]^T + b -> g_qkv
    {
        dim3 grid(QKV_OUT / 128, ROWS / 128);
        sgemm_nt_bias<<<grid, 256>>>(hidden, qkv_w, qkv_b, qkv_buf,
                                     ROWS, QKV_OUT, HIDDEN);
    }

    // 2) attention -> g_attn
    {
        dim3 grid(SEQ / BQ, NUM_H, BATCH);
        attn_kernel<<<grid, 256, attn_smem>>>(qkv_buf, scaling, attn_buf);
    }

    // 3) output projection: [8192,1280] x [1280,1280]^T + b -> out
    {
        dim3 grid(HIDDEN / 128, ROWS / 128);
        sgemm_nt_bias<<<grid, 256>>>(attn_buf, o_w, o_b, out,
                                     ROWS, HIDDEN, Q_SIZE);
    }
}

// round 2
// speedup vs baseline: 3.8653x; 3.8653x over previous
#include <cuda_runtime.h>
#include <math.h>

#define HIDDEN   1280
#define NUM_H    16
#define HDIM     80
#define Q_SIZE   1280
#define KV_SIZE  320
#define QKV_OUT  1920
#define BATCH    4
#define SEQ      2048
#define ROWS     8192

// Scratch (device globals — allocation-free rule)
__device__ float g_qkv[(size_t)ROWS * QKV_OUT];
__device__ float g_attn[(size_t)ROWS * Q_SIZE];

__device__ __forceinline__ unsigned f2tf(float f) {
    unsigned r; asm("cvt.rna.tf32.f32 %0, %1;" : "=r"(r) : "f"(f)); return r;
}

// D += A(16x8) * B(8x8), tf32 inputs, fp32 accum
__device__ __forceinline__ void mma8(float* c, const unsigned* a, const unsigned* b) {
    asm volatile(
        "mma.sync.aligned.m16n8k8.row.col.f32.tf32.tf32.f32 "
        "{%0,%1,%2,%3},{%4,%5,%6,%7},{%8,%9},{%0,%1,%2,%3};"
        : "+f"(c[0]), "+f"(c[1]), "+f"(c[2]), "+f"(c[3])
        : "r"(a[0]), "r"(a[1]), "r"(a[2]), "r"(a[3]), "r"(b[0]), "r"(b[1]));
}

// ---------------------------------------------------------------------------
// tf32 GEMM:  C[M,N] = A[M,K] * B[N,K]^T + bias[N]
// 128x128x16 tile, 256 threads (8 warps, 2x4), warp tile 64x32 (4x4 mma tiles)
// ---------------------------------------------------------------------------
#define GS 20   // smem k-stride (16 + 4 pad) -> conflict-free fragment reads

__global__ __launch_bounds__(256)
void gemm_tf32(const float* __restrict__ A, const float* __restrict__ B,
               const float* __restrict__ bias, float* __restrict__ C,
               int M, int N, int K)
{
    __shared__ unsigned As[2][128 * GS];
    __shared__ unsigned Bs[2][128 * GS];

    int tid  = threadIdx.x;
    int lane = tid & 31, wid = tid >> 5;
    int g = lane >> 2, t = lane & 3;
    int wm = wid >> 2;          // 0..1  (M)
    int wn = wid & 3;           // 0..3  (N)
    int row0 = blockIdx.y * 128;
    int col0 = blockIdx.x * 128;

    int lr = tid >> 2;          // 0..63
    int lc = (tid & 3) * 4;     // 0,4,8,12

    float acc[4][4][4];
#pragma unroll
    for (int i = 0; i < 4; i++)
#pragma unroll
        for (int j = 0; j < 4; j++)
#pragma unroll
            for (int r = 0; r < 4; r++) acc[i][j][r] = 0.f;

    const float* Ab = A + (size_t)row0 * K;
    const float* Bb = B + (size_t)col0 * K;

    float4 ra[2], rb[2];
    auto ldg_tile = [&](int kt) {
#pragma unroll
        for (int h = 0; h < 2; h++) {
            ra[h] = *(const float4*)&Ab[(size_t)(lr + 64 * h) * K + kt * 16 + lc];
            rb[h] = *(const float4*)&Bb[(size_t)(lr + 64 * h) * K + kt * 16 + lc];
        }
    };
    auto sts_tile = [&](int buf) {
#pragma unroll
        for (int h = 0; h < 2; h++) {
            uint4 ua = make_uint4(f2tf(ra[h].x), f2tf(ra[h].y), f2tf(ra[h].z), f2tf(ra[h].w));
            *(uint4*)&As[buf][(lr + 64 * h) * GS + lc] = ua;
            uint4 ub = make_uint4(f2tf(rb[h].x), f2tf(rb[h].y), f2tf(rb[h].z), f2tf(rb[h].w));
            *(uint4*)&Bs[buf][(lr + 64 * h) * GS + lc] = ub;
        }
    };

    int NT = K / 16;
    ldg_tile(0);
    sts_tile(0);
    __syncthreads();

    for (int kt = 0; kt < NT; kt++) {
        int buf = kt & 1;
        if (kt + 1 < NT) ldg_tile(kt + 1);

#pragma unroll
        for (int kk = 0; kk < 2; kk++) {
            unsigned af[4][4], bf[4][2];
#pragma unroll
            for (int mt = 0; mt < 4; mt++) {
                int rb2 = wm * 64 + mt * 16;
                af[mt][0] = As[buf][(rb2 + g)     * GS + kk * 8 + t];
                af[mt][1] = As[buf][(rb2 + g + 8) * GS + kk * 8 + t];
                af[mt][2] = As[buf][(rb2 + g)     * GS + kk * 8 + t + 4];
                af[mt][3] = As[buf][(rb2 + g + 8) * GS + kk * 8 + t + 4];
            }
#pragma unroll
            for (int nt = 0; nt < 4; nt++) {
                int nb = wn * 32 + nt * 8;
                bf[nt][0] = Bs[buf][(nb + g) * GS + kk * 8 + t];
                bf[nt][1] = Bs[buf][(nb + g) * GS + kk * 8 + t + 4];
            }
#pragma unroll
            for (int mt = 0; mt < 4; mt++)
#pragma unroll
                for (int nt = 0; nt < 4; nt++)
                    mma8(acc[mt][nt], af[mt], bf[nt]);
        }
        __syncthreads();
        if (kt + 1 < NT) sts_tile(buf ^ 1);
        __syncthreads();
    }

#pragma unroll
    for (int mt = 0; mt < 4; mt++) {
        int r = row0 + wm * 64 + mt * 16 + g;
#pragma unroll
        for (int nt = 0; nt < 4; nt++) {
            int c = col0 + wn * 32 + nt * 8 + 2 * t;
            float b0 = bias[c], b1 = bias[c + 1];
            *(float2*)&C[(size_t)r * N + c] =
                make_float2(acc[mt][nt][0] + b0, acc[mt][nt][1] + b1);
            *(float2*)&C[(size_t)(r + 8) * N + c] =
                make_float2(acc[mt][nt][2] + b0, acc[mt][nt][3] + b1);
        }
    }
}

// ---------------------------------------------------------------------------
// Tensor-core flash attention, tf32 MMA, fp32 softmax state.
// Block: 128 threads (4 warps), BQ=128 q-rows, BKV=64. Each warp owns 32 rows
// (2 m16 tiles). d=80 -> 10 n-tiles for PV, 10 k-steps for QK.
// Smem strides chosen conflict-free for the mma fragment access patterns.
// ---------------------------------------------------------------------------
#define QSTR 84
#define KSTR 84
#define VSTR 88
#define PSTR 68
#define ASMEM ((128*QSTR + 64*VSTR + 128*PSTR) * 4)   // 100352 bytes

__global__ __launch_bounds__(128)
void attn_tc(const float* __restrict__ qkv, const float* __restrict__ scaling,
             float* __restrict__ attn_out)
{
    extern __shared__ unsigned su[];
    unsigned* Qs = su;                  // [128][84]
    unsigned* KV = Qs + 128 * QSTR;     // [64][84] as K / [64][88] as V
    unsigned* Ps = KV + 64 * VSTR;      // [128][68]
    __shared__ float sscale[HDIM];

    int tid = threadIdx.x, lane = tid & 31, wid = tid >> 5;
    int g = lane >> 2, t = lane & 3;
    int q0 = blockIdx.x * 128;
    int h  = blockIdx.y;
    int b  = blockIdx.z;
    int kvh = h >> 2;

    if (tid < HDIM) {
        float x = scaling[tid];
        float sp = (x > 20.f) ? x : log1pf(__expf(x));
        sscale[tid] = 1.442695041f * rsqrtf((float)HDIM) * sp;
    }
    __syncthreads();

    // Q tile: scale + convert to tf32
    for (int i = tid * 4; i < 128 * HDIM; i += 128 * 4) {
        int r = i / HDIM, d = i % HDIM;
        float4 v = *(const float4*)&qkv[(size_t)(b * SEQ + q0 + r) * QKV_OUT + h * HDIM + d];
        uint4 u = make_uint4(f2tf(v.x * sscale[d]),     f2tf(v.y * sscale[d + 1]),
                             f2tf(v.z * sscale[d + 2]), f2tf(v.w * sscale[d + 3]));
        *(uint4*)&Qs[r * QSTR + d] = u;
    }

    float m_i[4], l_i[4];
    float oacc[2][10][4];
#pragma unroll
    for (int i = 0; i < 4; i++) { m_i[i] = -1e30f; l_i[i] = 0.f; }
#pragma unroll
    for (int mt = 0; mt < 2; mt++)
#pragma unroll
        for (int dn = 0; dn < 10; dn++)
#pragma unroll
            for (int r = 0; r < 4; r++) oacc[mt][dn][r] = 0.f;

    for (int k0 = 0; k0 < SEQ; k0 += 64) {
        __syncthreads();   // previous PV reads of KV/Ps complete
        // K tile
        for (int i = tid * 4; i < 64 * HDIM; i += 128 * 4) {
            int r = i / HDIM, d = i % HDIM;
            float4 v = *(const float4*)&qkv[(size_t)(b * SEQ + k0 + r) * QKV_OUT
                                            + Q_SIZE + kvh * HDIM + d];
            *(uint4*)&KV[r * KSTR + d] =
                make_uint4(f2tf(v.x), f2tf(v.y), f2tf(v.z), f2tf(v.w));
        }
        __syncthreads();

        // S = Q . K^T   (warp: 32 q-rows x 64 kv-cols)
        float sacc[2][8][4];
#pragma unroll
        for (int mt = 0; mt < 2; mt++)
#pragma unroll
            for (int nt = 0; nt < 8; nt++)
#pragma unroll
                for (int r = 0; r < 4; r++) sacc[mt][nt][r] = 0.f;

#pragma unroll
        for (int kk = 0; kk < 10; kk++) {
            unsigned af[2][4];
#pragma unroll
            for (int mt = 0; mt < 2; mt++) {
                int rb2 = wid * 32 + mt * 16;
                af[mt][0] = Qs[(rb2 + g)     * QSTR + kk * 8 + t];
                af[mt][1] = Qs[(rb2 + g + 8) * QSTR + kk * 8 + t];
                af[mt][2] = Qs[(rb2 + g)     * QSTR + kk * 8 + t + 4];
                af[mt][3] = Qs[(rb2 + g + 8) * QSTR + kk * 8 + t + 4];
            }
            unsigned bf[8][2];
#pragma unroll
            for (int nt = 0; nt < 8; nt++) {
                bf[nt][0] = KV[(nt * 8 + g) * KSTR + kk * 8 + t];
                bf[nt][1] = KV[(nt * 8 + g) * KSTR + kk * 8 + t + 4];
            }
#pragma unroll
            for (int mt = 0; mt < 2; mt++)
#pragma unroll
                for (int nt = 0; nt < 8; nt++)
                    mma8(sacc[mt][nt], af[mt], bf[nt]);
        }

        // online softmax; write P (tf32) to smem
#pragma unroll
        for (int mt = 0; mt < 2; mt++) {
            float mx0 = -1e30f, mx1 = -1e30f;
#pragma unroll
            for (int nt = 0; nt < 8; nt++) {
                mx0 = fmaxf(mx0, fmaxf(sacc[mt][nt][0], sacc[mt][nt][1]));
                mx1 = fmaxf(mx1, fmaxf(sacc[mt][nt][2], sacc[mt][nt][3]));
            }
            mx0 = fmaxf(mx0, __shfl_xor_sync(0xffffffffu, mx0, 1));
            mx0 = fmaxf(mx0, __shfl_xor_sync(0xffffffffu, mx0, 2));
            mx1 = fmaxf(mx1, __shfl_xor_sync(0xffffffffu, mx1, 1));
            mx1 = fmaxf(mx1, __shfl_xor_sync(0xffffffffu, mx1, 2));

            int s0 = mt * 2, s1 = mt * 2 + 1;
            float mn0 = fmaxf(m_i[s0], mx0), mn1 = fmaxf(m_i[s1], mx1);
            float a0 = __expf(m_i[s0] - mn0), a1 = __expf(m_i[s1] - mn1);
            m_i[s0] = mn0; m_i[s1] = mn1;

            float rs0 = 0.f, rs1 = 0.f;
            int rb2 = wid * 32 + mt * 16;
#pragma unroll
            for (int nt = 0; nt < 8; nt++) {
                float p0 = __expf(sacc[mt][nt][0] - mn0);
                float p1 = __expf(sacc[mt][nt][1] - mn0);
                float p2 = __expf(sacc[mt][nt][2] - mn1);
                float p3 = __expf(sacc[mt][nt][3] - mn1);
                rs0 += p0 + p1; rs1 += p2 + p3;
                *(uint2*)&Ps[(rb2 + g)     * PSTR + nt * 8 + 2 * t] = make_uint2(f2tf(p0), f2tf(p1));
                *(uint2*)&Ps[(rb2 + g + 8) * PSTR + nt * 8 + 2 * t] = make_uint2(f2tf(p2), f2tf(p3));
            }
            rs0 += __shfl_xor_sync(0xffffffffu, rs0, 1);
            rs0 += __shfl_xor_sync(0xffffffffu, rs0, 2);
            rs1 += __shfl_xor_sync(0xffffffffu, rs1, 1);
            rs1 += __shfl_xor_sync(0xffffffffu, rs1, 2);
            l_i[s0] = l_i[s0] * a0 + rs0;
            l_i[s1] = l_i[s1] * a1 + rs1;
#pragma unroll
            for (int dn = 0; dn < 10; dn++) {
                oacc[mt][dn][0] *= a0; oacc[mt][dn][1] *= a0;
                oacc[mt][dn][2] *= a1; oacc[mt][dn][3] *= a1;
            }
        }
        __syncthreads();   // Ps written; K reads done -> reuse KV for V

        // V tile
        for (int i = tid * 4; i < 64 * HDIM; i += 128 * 4) {
            int r = i / HDIM, d = i % HDIM;
            float4 v = *(const float4*)&qkv[(size_t)(b * SEQ + k0 + r) * QKV_OUT
                                            + Q_SIZE + KV_SIZE + kvh * HDIM + d];
            *(uint4*)&KV[r * VSTR + d] =
                make_uint4(f2tf(v.x), f2tf(v.y), f2tf(v.z), f2tf(v.w));
        }
        __syncthreads();

        // O += P . V
#pragma unroll
        for (int kk = 0; kk < 8; kk++) {
            unsigned af[2][4];
#pragma unroll
            for (int mt = 0; mt < 2; mt++) {
                int rb2 = wid * 32 + mt * 16;
                af[mt][0] = Ps[(rb2 + g)     * PSTR + kk * 8 + t];
                af[mt][1] = Ps[(rb2 + g + 8) * PSTR + kk * 8 + t];
                af[mt][2] = Ps[(rb2 + g)     * PSTR + kk * 8 + t + 4];
                af[mt][3] = Ps[(rb2 + g + 8) * PSTR + kk * 8 + t + 4];
            }
            unsigned bf[10][2];
#pragma unroll
            for (int dn = 0; dn < 10; dn++) {
                bf[dn][0] = KV[(kk * 8 + t)     * VSTR + dn * 8 + g];
                bf[dn][1] = KV[(kk * 8 + t + 4) * VSTR + dn * 8 + g];
            }
#pragma unroll
            for (int mt = 0; mt < 2; mt++)
#pragma unroll
                for (int dn = 0; dn < 10; dn++)
                    mma8(oacc[mt][dn], af[mt], bf[dn]);
        }
    }

    // normalize + write
#pragma unroll
    for (int mt = 0; mt < 2; mt++) {
        float inv0 = 1.f / l_i[mt * 2], inv1 = 1.f / l_i[mt * 2 + 1];
        int r = q0 + wid * 32 + mt * 16 + g;
#pragma unroll
        for (int dn = 0; dn < 10; dn++) {
            int c = h * HDIM + dn * 8 + 2 * t;
            *(float2*)&attn_out[(size_t)(b * SEQ + r) * Q_SIZE + c] =
                make_float2(oacc[mt][dn][0] * inv0, oacc[mt][dn][1] * inv0);
            *(float2*)&attn_out[(size_t)(b * SEQ + r + 8) * Q_SIZE + c] =
                make_float2(oacc[mt][dn][2] * inv1, oacc[mt][dn][3] * inv1);
        }
    }
}

// ---------------------------------------------------------------------------
extern "C" void kernel_launch(void* const* d_in, const int* in_sizes, int n_in,
                              void* d_out, int out_size)
{
    const float* hidden  = (const float*)d_in[0];
    const float* scaling = (const float*)d_in[1];
    const float* qkv_w   = (const float*)d_in[2];
    const float* qkv_b   = (const float*)d_in[3];
    const float* o_w     = (const float*)d_in[4];
    const float* o_b     = (const float*)d_in[5];
    float* out = (float*)d_out;

    float* qkv_buf = nullptr;
    float* attn_buf = nullptr;
    cudaGetSymbolAddress((void**)&qkv_buf, g_qkv);
    cudaGetSymbolAddress((void**)&attn_buf, g_attn);

    static bool attr_set = false;
    if (!attr_set) {
        cudaFuncSetAttribute(attn_tc,
                             cudaFuncAttributeMaxDynamicSharedMemorySize, ASMEM);
        attr_set = true;
    }

    {   // QKV projection
        dim3 grid(QKV_OUT / 128, ROWS / 128);
        gemm_tf32<<<grid, 256>>>(hidden, qkv_w, qkv_b, qkv_buf,
                                 ROWS, QKV_OUT, HIDDEN);
    }
    {   // attention
        dim3 grid(SEQ / 128, NUM_H, BATCH);
        attn_tc<<<grid, 128, ASMEM>>>(qkv_buf, scaling, attn_buf);
    }
    {   // output projection
        dim3 grid(HIDDEN / 128, ROWS / 128);
        gemm_tf32<<<grid, 256>>>(attn_buf, o_w, o_b, out,
                                 ROWS, HIDDEN, Q_SIZE);
    }
}

// round 3
// speedup vs baseline: 5.0265x; 1.3004x over previous
#include <cuda_runtime.h>
#include <math.h>

#define HIDDEN   1280
#define NUM_H    16
#define HDIM     80
#define Q_SIZE   1280
#define KV_SIZE  320
#define QKV_OUT  1920
#define BATCH    4
#define SEQ      2048
#define ROWS     8192

// Scratch (device globals — allocation-free rule)
__device__ unsigned g_hidc[(size_t)ROWS * HIDDEN];      // hidden, tf32 bits
__device__ unsigned g_wqkv[(size_t)QKV_OUT * HIDDEN];   // qkv_w, scaled+tf32
__device__ float    g_bqkv[QKV_OUT];                    // qkv_b, scaled
__device__ unsigned g_wo[(size_t)HIDDEN * Q_SIZE];      // o_w, tf32
__device__ unsigned g_qkv[(size_t)ROWS * QKV_OUT];      // qkv out, tf32 bits
__device__ unsigned g_attn[(size_t)ROWS * Q_SIZE];      // attn out, tf32 bits
__device__ float    g_scale[HDIM];

__device__ __forceinline__ unsigned f2tf(float f) {
    unsigned r; asm("cvt.rna.tf32.f32 %0, %1;" : "=r"(r) : "f"(f)); return r;
}
__device__ __forceinline__ void mma8(float* c, const unsigned* a, const unsigned* b) {
    asm volatile(
        "mma.sync.aligned.m16n8k8.row.col.f32.tf32.tf32.f32 "
        "{%0,%1,%2,%3},{%4,%5,%6,%7},{%8,%9},{%0,%1,%2,%3};"
        : "+f"(c[0]), "+f"(c[1]), "+f"(c[2]), "+f"(c[3])
        : "r"(a[0]), "r"(a[1]), "r"(a[2]), "r"(a[3]), "r"(b[0]), "r"(b[1]));
}
__device__ __forceinline__ void ldsm4(unsigned* r, unsigned addr) {
    asm volatile("ldmatrix.sync.aligned.m8n8.x4.shared.b16 {%0,%1,%2,%3}, [%4];"
        : "=r"(r[0]), "=r"(r[1]), "=r"(r[2]), "=r"(r[3]) : "r"(addr));
}
__device__ __forceinline__ void cpa16(unsigned dst, const void* src) {
    asm volatile("cp.async.cg.shared.global [%0], [%1], 16;" :: "r"(dst), "l"(src));
}
__device__ __forceinline__ void cp_commit() {
    asm volatile("cp.async.commit_group;");
}
template<int N> __device__ __forceinline__ void cp_wait() {
    asm volatile("cp.async.wait_group %0;" :: "n"(N));
}

// ---------------------------------------------------------------------------
// Prep kernels
// ---------------------------------------------------------------------------
__global__ void k_scale(const float* __restrict__ scaling) {
    int i = threadIdx.x;
    if (i < HDIM) {
        float x = scaling[i];
        float sp = (x > 20.f) ? x : log1pf(__expf(x));
        g_scale[i] = 1.442695041f * rsqrtf((float)HDIM) * sp;
    }
}
__global__ void k_conv(const float* __restrict__ src, unsigned* __restrict__ dst, int n4) {
    for (int i = blockIdx.x * blockDim.x + threadIdx.x; i < n4; i += gridDim.x * blockDim.x) {
        float4 v = ((const float4*)src)[i];
        ((uint4*)dst)[i] = make_uint4(f2tf(v.x), f2tf(v.y), f2tf(v.z), f2tf(v.w));
    }
}
__global__ void k_conv_wqkv(const float* __restrict__ w, const float* __restrict__ bsrc) {
    int gid = blockIdx.x * blockDim.x + threadIdx.x;
    const int n4 = QKV_OUT * HIDDEN / 4;
    for (int j = gid; j < n4; j += gridDim.x * blockDim.x) {
        int row = (j * 4) / HIDDEN;
        float s = (row < Q_SIZE) ? g_scale[row % HDIM] : 1.f;
        float4 v = ((const float4*)w)[j];
        ((uint4*)g_wqkv)[j] = make_uint4(f2tf(v.x * s), f2tf(v.y * s),
                                         f2tf(v.z * s), f2tf(v.w * s));
    }
    if (gid < QKV_OUT) {
        float s = (gid < Q_SIZE) ? g_scale[gid % HDIM] : 1.f;
        g_bqkv[gid] = bsrc[gid] * s;
    }
}

// ---------------------------------------------------------------------------
// tf32 GEMM:  C[M,N] = A[M,K] * B[N,K]^T + bias[N]
// A,B pre-converted tf32 bits. 128x128x16 tile, 3-stage cp.async, ldmatrix.
// 256 threads (8 warps 2x4), warp tile 64x32.
// ---------------------------------------------------------------------------
#define GS   20
#define GSTG 5120   // words per stage (A 128*20 + B 128*20)
#define GSMEM (3 * GSTG * 4)

template<bool ROUND_OUT>
__global__ __launch_bounds__(256, 2)
void gemm_tc(const unsigned* __restrict__ A, const unsigned* __restrict__ B,
             const float* __restrict__ bias, float* __restrict__ C,
             int M, int N, int K)
{
    extern __shared__ unsigned smg[];
    unsigned sb = (unsigned)__cvta_generic_to_shared(smg);

    int tid = threadIdx.x, lane = tid & 31, wid = tid >> 5;
    int g = lane >> 2, t = lane & 3;
    int wm = wid >> 2, wn = wid & 3;
    int row0 = blockIdx.y * 128, col0 = blockIdx.x * 128;
    int lr = tid >> 2, lc = (tid & 3) * 4;

    const unsigned* Ab = A + (size_t)row0 * K + (size_t)lr * K + lc;
    const unsigned* Bb = B + (size_t)col0 * K + (size_t)lr * K + lc;
    int NT = K / 16;

    int ar = lane & 15, ac = (lane >> 4) * 4;
    int br = (lane & 7) + (lane >> 4) * 8, bc = ((lane >> 3) & 1) * 4;

    // prologue: stages 0,1
#pragma unroll
    for (int s = 0; s < 2; s++) {
        unsigned da = sb + (s * GSTG + lr * GS + lc) * 4;
        unsigned db = sb + (s * GSTG + 2560 + lr * GS + lc) * 4;
        cpa16(da,               Ab + s * 16);
        cpa16(da + 64 * GS * 4, Ab + (size_t)64 * K + s * 16);
        cpa16(db,               Bb + s * 16);
        cpa16(db + 64 * GS * 4, Bb + (size_t)64 * K + s * 16);
        cp_commit();
    }

    float acc[4][4][4];
#pragma unroll
    for (int i = 0; i < 4; i++)
#pragma unroll
        for (int j = 0; j < 4; j++)
#pragma unroll
            for (int r = 0; r < 4; r++) acc[i][j][r] = 0.f;

    for (int kt = 0; kt < NT; kt++) {
        if (kt + 1 < NT) cp_wait<1>(); else cp_wait<0>();
        __syncthreads();

        if (kt + 2 < NT) {
            int s = (kt + 2) % 3;
            unsigned da = sb + (s * GSTG + lr * GS + lc) * 4;
            unsigned db = sb + (s * GSTG + 2560 + lr * GS + lc) * 4;
            cpa16(da,               Ab + (kt + 2) * 16);
            cpa16(da + 64 * GS * 4, Ab + (size_t)64 * K + (kt + 2) * 16);
            cpa16(db,               Bb + (kt + 2) * 16);
            cpa16(db + 64 * GS * 4, Bb + (size_t)64 * K + (kt + 2) * 16);
            cp_commit();
        }

        unsigned abase = sb + ((kt % 3) * GSTG) * 4;
        unsigned bbase = abase + 2560 * 4;
#pragma unroll
        for (int kk = 0; kk < 2; kk++) {
            unsigned af[4][4];
#pragma unroll
            for (int mt = 0; mt < 4; mt++)
                ldsm4(af[mt], abase + (((wm * 64 + mt * 16 + ar) * GS) + kk * 8 + ac) * 4);
            unsigned bf[4][2];
#pragma unroll
            for (int p = 0; p < 2; p++) {
                unsigned r[4];
                ldsm4(r, bbase + (((wn * 32 + p * 16 + br) * GS) + kk * 8 + bc) * 4);
                bf[2 * p][0] = r[0]; bf[2 * p][1] = r[1];
                bf[2 * p + 1][0] = r[2]; bf[2 * p + 1][1] = r[3];
            }
#pragma unroll
            for (int mt = 0; mt < 4; mt++)
#pragma unroll
                for (int nt = 0; nt < 4; nt++)
                    mma8(acc[mt][nt], af[mt], bf[nt]);
        }
    }

#pragma unroll
    for (int mt = 0; mt < 4; mt++) {
        int r = row0 + wm * 64 + mt * 16 + g;
#pragma unroll
        for (int nt = 0; nt < 4; nt++) {
            int c = col0 + wn * 32 + nt * 8 + 2 * t;
            float b0 = bias[c], b1 = bias[c + 1];
            float v00 = acc[mt][nt][0] + b0, v01 = acc[mt][nt][1] + b1;
            float v10 = acc[mt][nt][2] + b0, v11 = acc[mt][nt][3] + b1;
            if (ROUND_OUT) {
                v00 = __uint_as_float(f2tf(v00)); v01 = __uint_as_float(f2tf(v01));
                v10 = __uint_as_float(f2tf(v10)); v11 = __uint_as_float(f2tf(v11));
            }
            *(float2*)&C[(size_t)r * N + c]       = make_float2(v00, v01);
            *(float2*)&C[(size_t)(r + 8) * N + c] = make_float2(v10, v11);
        }
    }
}

// ---------------------------------------------------------------------------
// Flash attention, tf32 MMA, cp.async pipeline. BQ=256, 8 warps (32 rows each).
// smem words: Q[256][84] | K0[64][84] | K1[64][84] | V[64][88] | P[256][68]
// ---------------------------------------------------------------------------
#define QSTR 84
#define VSTR 88
#define PSTR 68
#define K0OFF (256 * QSTR)            // 21504
#define K1OFF (K0OFF + 64 * QSTR)     // 26880
#define VOFF  (K1OFF + 64 * QSTR)     // 32256
#define POFF  (VOFF + 64 * VSTR)      // 37888
#define ASMEM ((POFF + 256 * PSTR) * 4)  // 221184 bytes

__global__ __launch_bounds__(256)
void attn_tc(const unsigned* __restrict__ qkv, unsigned* __restrict__ attn_out)
{
    extern __shared__ unsigned sm[];
    unsigned sb = (unsigned)__cvta_generic_to_shared(sm);

    int tid = threadIdx.x, lane = tid & 31, wid = tid >> 5;
    int g = lane >> 2, t = lane & 3;
    int q0 = blockIdx.x * 256;
    int h = blockIdx.y, b = blockIdx.z, kvh = h >> 2;
    int wr0 = wid * 32;

    int ar = lane & 15, ac = (lane >> 4) * 4;
    int br = (lane & 7) + (lane >> 4) * 8, bc = ((lane >> 3) & 1) * 4;

    const unsigned* qg = qkv + (size_t)(b * SEQ + q0) * QKV_OUT + h * HDIM;
    const unsigned* kg = qkv + (size_t)(b * SEQ) * QKV_OUT + Q_SIZE + kvh * HDIM;
    const unsigned* vg = kg + KV_SIZE;

    // prologue: Q + K(0)  (one group)
    for (int i = tid * 4; i < 256 * HDIM; i += 1024) {
        int r = i / HDIM, d = i % HDIM;
        cpa16(sb + (r * QSTR + d) * 4, qg + (size_t)r * QKV_OUT + d);
    }
    for (int i = tid * 4; i < 64 * HDIM; i += 1024) {
        int r = i / HDIM, d = i % HDIM;
        cpa16(sb + (K0OFF + r * QSTR + d) * 4, kg + (size_t)r * QKV_OUT + d);
    }
    cp_commit();

    float m_i[4], l_i[4], oacc[2][10][4];
#pragma unroll
    for (int i = 0; i < 4; i++) { m_i[i] = -1e30f; l_i[i] = 0.f; }
#pragma unroll
    for (int mt = 0; mt < 2; mt++)
#pragma unroll
        for (int dn = 0; dn < 10; dn++)
#pragma unroll
            for (int r = 0; r < 4; r++) oacc[mt][dn][r] = 0.f;

    for (int kt = 0; kt < SEQ / 64; kt++) {
        cp_wait<0>();          // K(kt) (and prior V) complete
        __syncthreads();       // [A]

        // issue V(kt)
        for (int i = tid * 4; i < 64 * HDIM; i += 1024) {
            int r = i / HDIM, d = i % HDIM;
            cpa16(sb + (VOFF + r * VSTR + d) * 4,
                  vg + (size_t)(kt * 64 + r) * QKV_OUT + d);
        }
        cp_commit();

        unsigned kbase = sb + ((kt & 1) ? K1OFF : K0OFF) * 4;

        // S = Q . K^T
        float sacc[2][8][4];
#pragma unroll
        for (int mt = 0; mt < 2; mt++)
#pragma unroll
            for (int nt = 0; nt < 8; nt++)
#pragma unroll
                for (int r = 0; r < 4; r++) sacc[mt][nt][r] = 0.f;

#pragma unroll
        for (int kk = 0; kk < 10; kk++) {
            unsigned qa[2][4];
#pragma unroll
            for (int mt = 0; mt < 2; mt++)
                ldsm4(qa[mt], sb + (((wr0 + mt * 16 + ar) * QSTR) + kk * 8 + ac) * 4);
            unsigned kb[8][2];
#pragma unroll
            for (int p = 0; p < 4; p++) {
                unsigned r[4];
                ldsm4(r, kbase + (((p * 16 + br) * QSTR) + kk * 8 + bc) * 4);
                kb[2 * p][0] = r[0]; kb[2 * p][1] = r[1];
                kb[2 * p + 1][0] = r[2]; kb[2 * p + 1][1] = r[3];
            }
#pragma unroll
            for (int mt = 0; mt < 2; mt++)
#pragma unroll
                for (int nt = 0; nt < 8; nt++)
                    mma8(sacc[mt][nt], qa[mt], kb[nt]);
        }

        // online softmax; write P (tf32) to smem (own-warp rows only)
#pragma unroll
        for (int mt = 0; mt < 2; mt++) {
            float mx0 = -1e30f, mx1 = -1e30f;
#pragma unroll
            for (int nt = 0; nt < 8; nt++) {
                mx0 = fmaxf(mx0, fmaxf(sacc[mt][nt][0], sacc[mt][nt][1]));
                mx1 = fmaxf(mx1, fmaxf(sacc[mt][nt][2], sacc[mt][nt][3]));
            }
            mx0 = fmaxf(mx0, __shfl_xor_sync(0xffffffffu, mx0, 1));
            mx0 = fmaxf(mx0, __shfl_xor_sync(0xffffffffu, mx0, 2));
            mx1 = fmaxf(mx1, __shfl_xor_sync(0xffffffffu, mx1, 1));
            mx1 = fmaxf(mx1, __shfl_xor_sync(0xffffffffu, mx1, 2));

            int s0 = mt * 2, s1 = mt * 2 + 1;
            float mn0 = fmaxf(m_i[s0], mx0), mn1 = fmaxf(m_i[s1], mx1);
            float a0 = __expf(m_i[s0] - mn0), a1 = __expf(m_i[s1] - mn1);
            m_i[s0] = mn0; m_i[s1] = mn1;

            float rs0 = 0.f, rs1 = 0.f;
            int rb2 = wr0 + mt * 16;
#pragma unroll
            for (int nt = 0; nt < 8; nt++) {
                float p0 = __expf(sacc[mt][nt][0] - mn0);
                float p1 = __expf(sacc[mt][nt][1] - mn0);
                float p2 = __expf(sacc[mt][nt][2] - mn1);
                float p3 = __expf(sacc[mt][nt][3] - mn1);
                rs0 += p0 + p1; rs1 += p2 + p3;
                *(uint2*)&sm[POFF + (rb2 + g) * PSTR + nt * 8 + 2 * t] =
                    make_uint2(f2tf(p0), f2tf(p1));
                *(uint2*)&sm[POFF + (rb2 + g + 8) * PSTR + nt * 8 + 2 * t] =
                    make_uint2(f2tf(p2), f2tf(p3));
            }
            rs0 += __shfl_xor_sync(0xffffffffu, rs0, 1);
            rs0 += __shfl_xor_sync(0xffffffffu, rs0, 2);
            rs1 += __shfl_xor_sync(0xffffffffu, rs1, 1);
            rs1 += __shfl_xor_sync(0xffffffffu, rs1, 2);
            l_i[s0] = l_i[s0] * a0 + rs0;
            l_i[s1] = l_i[s1] * a1 + rs1;
#pragma unroll
            for (int dn = 0; dn < 10; dn++) {
                oacc[mt][dn][0] *= a0; oacc[mt][dn][1] *= a0;
                oacc[mt][dn][2] *= a1; oacc[mt][dn][3] *= a1;
            }
        }

        // issue K(kt+1); wait V(kt)
        if (kt + 1 < SEQ / 64) {
            unsigned kdst = sb + (((kt + 1) & 1) ? K1OFF : K0OFF) * 4;
            for (int i = tid * 4; i < 64 * HDIM; i += 1024) {
                int r = i / HDIM, d = i % HDIM;
                cpa16(kdst + (r * QSTR + d) * 4,
                      kg + (size_t)((kt + 1) * 64 + r) * QKV_OUT + d);
            }
            cp_commit();
            cp_wait<1>();      // V(kt) done (K(kt+1) may remain pending)
        } else {
            cp_wait<0>();
        }
        __syncthreads();       // [C] V + P visible

        // O += P . V
#pragma unroll
        for (int kk = 0; kk < 8; kk++) {
            unsigned pa[2][4];
#pragma unroll
            for (int mt = 0; mt < 2; mt++)
                ldsm4(pa[mt], sb + ((POFF + (wr0 + mt * 16 + ar) * PSTR) + kk * 8 + ac) * 4);
            unsigned vb[10][2];
#pragma unroll
            for (int dn = 0; dn < 10; dn++) {
                vb[dn][0] = sm[VOFF + (kk * 8 + t) * VSTR + dn * 8 + g];
                vb[dn][1] = sm[VOFF + (kk * 8 + t + 4) * VSTR + dn * 8 + g];
            }
#pragma unroll
            for (int mt = 0; mt < 2; mt++)
#pragma unroll
                for (int dn = 0; dn < 10; dn++)
                    mma8(oacc[mt][dn], pa[mt], vb[dn]);
        }
    }

    // normalize + write tf32 bits (feeds O-proj cp.async)
#pragma unroll
    for (int mt = 0; mt < 2; mt++) {
        float inv0 = 1.f / l_i[mt * 2], inv1 = 1.f / l_i[mt * 2 + 1];
        int r = q0 + wr0 + mt * 16 + g;
#pragma unroll
        for (int dn = 0; dn < 10; dn++) {
            int c = h * HDIM + dn * 8 + 2 * t;
            *(uint2*)&attn_out[(size_t)(b * SEQ + r) * Q_SIZE + c] =
                make_uint2(f2tf(oacc[mt][dn][0] * inv0), f2tf(oacc[mt][dn][1] * inv0));
            *(uint2*)&attn_out[(size_t)(b * SEQ + r + 8) * Q_SIZE + c] =
                make_uint2(f2tf(oacc[mt][dn][2] * inv1), f2tf(oacc[mt][dn][3] * inv1));
        }
    }
}

// ---------------------------------------------------------------------------
extern "C" void kernel_launch(void* const* d_in, const int* in_sizes, int n_in,
                              void* d_out, int out_size)
{
    const float* hidden  = (const float*)d_in[0];
    const float* scaling = (const float*)d_in[1];
    const float* qkv_w   = (const float*)d_in[2];
    const float* qkv_b   = (const float*)d_in[3];
    const float* o_w     = (const float*)d_in[4];
    const float* o_b     = (const float*)d_in[5];
    float* out = (float*)d_out;

    unsigned *hidc, *wqkv, *wo, *qkvb, *attnb;
    float *bqkv;
    cudaGetSymbolAddress((void**)&hidc,  g_hidc);
    cudaGetSymbolAddress((void**)&wqkv,  g_wqkv);
    cudaGetSymbolAddress((void**)&bqkv,  g_bqkv);
    cudaGetSymbolAddress((void**)&wo,    g_wo);
    cudaGetSymbolAddress((void**)&qkvb,  g_qkv);
    cudaGetSymbolAddress((void**)&attnb, g_attn);

    static bool attr_set = false;
    if (!attr_set) {
        cudaFuncSetAttribute(attn_tc,
                             cudaFuncAttributeMaxDynamicSharedMemorySize, ASMEM);
        cudaFuncSetAttribute(gemm_tc<true>,
                             cudaFuncAttributeMaxDynamicSharedMemorySize, GSMEM);
        cudaFuncSetAttribute(gemm_tc<false>,
                             cudaFuncAttributeMaxDynamicSharedMemorySize, GSMEM);
        attr_set = true;
    }

    // 0) prep: scale, conversions
    k_scale<<<1, 128>>>(scaling);
    k_conv<<<2048, 256>>>(hidden, hidc, ROWS * HIDDEN / 4);
    k_conv_wqkv<<<1200, 512>>>(qkv_w, qkv_b);
    k_conv<<<800, 512>>>(o_w, wo, HIDDEN * Q_SIZE / 4);

    // 1) QKV projection -> g_qkv (tf32-rounded)
    {
        dim3 grid(QKV_OUT / 128, ROWS / 128);
        gemm_tc<true><<<grid, 256, GSMEM>>>(hidc, wqkv, bqkv, (float*)qkvb,
                                            ROWS, QKV_OUT, HIDDEN);
    }
    // 2) attention -> g_attn (tf32-rounded)
    {
        dim3 grid(SEQ / 256, NUM_H, BATCH);
        attn_tc<<<grid, 256, ASMEM>>>(qkvb, attnb);
    }
    // 3) output projection -> out (fp32)
    {
        dim3 grid(HIDDEN / 128, ROWS / 128);
        gemm_tc<false><<<grid, 256, GSMEM>>>(attnb, wo, o_b, out,
                                             ROWS, HIDDEN, Q_SIZE);
    }
}

// round 4
// speedup vs baseline: 5.1705x; 1.0287x over previous
#include <cuda_runtime.h>
#include <math.h>

#define HIDDEN   1280
#define NUM_H    16
#define HDIM     80
#define Q_SIZE   1280
#define KV_SIZE  320
#define QKV_OUT  1920
#define BATCH    4
#define SEQ      2048
#define ROWS     8192

// Scratch (device globals — allocation-free rule)
__device__ unsigned g_hidc[(size_t)ROWS * HIDDEN];      // hidden, tf32 bits
__device__ unsigned g_wqkv[(size_t)QKV_OUT * HIDDEN];   // qkv_w, scaled+tf32
__device__ float    g_bqkv[QKV_OUT];                    // qkv_b, scaled
__device__ unsigned g_wo[(size_t)HIDDEN * Q_SIZE];      // o_w, tf32
__device__ unsigned g_qkv[(size_t)ROWS * QKV_OUT];      // qkv out, tf32 bits
__device__ unsigned g_vT[(size_t)BATCH * 4 * HDIM * SEQ]; // V transposed
__device__ unsigned g_attn[(size_t)ROWS * Q_SIZE];      // attn out, tf32 bits

__device__ __forceinline__ unsigned f2tf(float f) {
    unsigned r; asm("cvt.rna.tf32.f32 %0, %1;" : "=r"(r) : "f"(f)); return r;
}
__device__ __forceinline__ void mma8(float* c, const unsigned* a, const unsigned* b) {
    asm volatile(
        "mma.sync.aligned.m16n8k8.row.col.f32.tf32.tf32.f32 "
        "{%0,%1,%2,%3},{%4,%5,%6,%7},{%8,%9},{%0,%1,%2,%3};"
        : "+f"(c[0]), "+f"(c[1]), "+f"(c[2]), "+f"(c[3])
        : "r"(a[0]), "r"(a[1]), "r"(a[2]), "r"(a[3]), "r"(b[0]), "r"(b[1]));
}
__device__ __forceinline__ void ldsm4(unsigned* r, unsigned addr) {
    asm volatile("ldmatrix.sync.aligned.m8n8.x4.shared.b16 {%0,%1,%2,%3}, [%4];"
        : "=r"(r[0]), "=r"(r[1]), "=r"(r[2]), "=r"(r[3]) : "r"(addr));
}
__device__ __forceinline__ void cpa16(unsigned dst, const void* src) {
    asm volatile("cp.async.cg.shared.global [%0], [%1], 16;" :: "r"(dst), "l"(src));
}
__device__ __forceinline__ void cp_commit() {
    asm volatile("cp.async.commit_group;");
}
template<int N> __device__ __forceinline__ void cp_wait() {
    asm volatile("cp.async.wait_group %0;" :: "n"(N));
}

// ---------------------------------------------------------------------------
// Prep kernels
// ---------------------------------------------------------------------------
__global__ void k_conv(const float* __restrict__ src, unsigned* __restrict__ dst, int n4) {
    for (int i = blockIdx.x * blockDim.x + threadIdx.x; i < n4; i += gridDim.x * blockDim.x) {
        float4 v = ((const float4*)src)[i];
        ((uint4*)dst)[i] = make_uint4(f2tf(v.x), f2tf(v.y), f2tf(v.z), f2tf(v.w));
    }
}
__device__ __forceinline__ float head_scale(const float* scaling, int row) {
    if (row >= Q_SIZE) return 1.f;
    float x = scaling[row % HDIM];
    float sp = (x > 20.f) ? x : log1pf(__expf(x));
    return 1.442695041f * rsqrtf((float)HDIM) * sp;
}
__global__ void k_conv_wqkv(const float* __restrict__ w, const float* __restrict__ bsrc,
                            const float* __restrict__ scaling) {
    int gid = blockIdx.x * blockDim.x + threadIdx.x;
    const int n4 = QKV_OUT * HIDDEN / 4;
    for (int j = gid; j < n4; j += gridDim.x * blockDim.x) {
        int row = (j * 4) / HIDDEN;
        float s = head_scale(scaling, row);
        float4 v = ((const float4*)w)[j];
        ((uint4*)g_wqkv)[j] = make_uint4(f2tf(v.x * s), f2tf(v.y * s),
                                         f2tf(v.z * s), f2tf(v.w * s));
    }
    if (gid < QKV_OUT)
        g_bqkv[gid] = bsrc[gid] * head_scale(scaling, gid);
}

// Transpose V section of g_qkv -> g_vT[(b*4+kvh)][d][s]
__global__ void k_vT(const unsigned* __restrict__ qkv, unsigned* __restrict__ vT) {
    __shared__ unsigned tile[32][33];
    int bz = blockIdx.z, b = bz >> 2, kvh = bz & 3;
    int s0 = blockIdx.x * 32, d0 = blockIdx.y * 32;
    int tx = threadIdx.x, ty = threadIdx.y;   // 32 x 8
    const unsigned* src = qkv + (size_t)(b * SEQ) * QKV_OUT + Q_SIZE + KV_SIZE + kvh * HDIM;
#pragma unroll
    for (int i = 0; i < 32; i += 8) {
        int d = d0 + tx, s = s0 + ty + i;
        if (d < HDIM) tile[ty + i][tx] = src[(size_t)s * QKV_OUT + d];
    }
    __syncthreads();
    unsigned* dst = vT + (size_t)bz * HDIM * SEQ;
#pragma unroll
    for (int i = 0; i < 32; i += 8) {
        int d = d0 + ty + i, s = s0 + tx;
        if (d < HDIM) dst[(size_t)d * SEQ + s] = tile[tx][ty + i];
    }
}

// ---------------------------------------------------------------------------
// tf32 GEMM:  C[M,N] = A[M,K] * B[N,K]^T + bias[N]  (3-stage cp.async, ldsm)
// ---------------------------------------------------------------------------
#define GS   20
#define GSTG 5120
#define GSMEM (3 * GSTG * 4)

template<bool ROUND_OUT>
__global__ __launch_bounds__(256, 2)
void gemm_tc(const unsigned* __restrict__ A, const unsigned* __restrict__ B,
             const float* __restrict__ bias, float* __restrict__ C,
             int M, int N, int K)
{
    extern __shared__ unsigned smg[];
    unsigned sb = (unsigned)__cvta_generic_to_shared(smg);

    int tid = threadIdx.x, lane = tid & 31, wid = tid >> 5;
    int g = lane >> 2, t = lane & 3;
    int wm = wid >> 2, wn = wid & 3;
    int row0 = blockIdx.y * 128, col0 = blockIdx.x * 128;
    int lr = tid >> 2, lc = (tid & 3) * 4;

    const unsigned* Ab = A + (size_t)row0 * K + (size_t)lr * K + lc;
    const unsigned* Bb = B + (size_t)col0 * K + (size_t)lr * K + lc;
    int NT = K / 16;

    int ar = lane & 15, ac = (lane >> 4) * 4;
    int br = (lane & 7) + (lane >> 4) * 8, bc = ((lane >> 3) & 1) * 4;

#pragma unroll
    for (int s = 0; s < 2; s++) {
        unsigned da = sb + (s * GSTG + lr * GS + lc) * 4;
        unsigned db = sb + (s * GSTG + 2560 + lr * GS + lc) * 4;
        cpa16(da,               Ab + s * 16);
        cpa16(da + 64 * GS * 4, Ab + (size_t)64 * K + s * 16);
        cpa16(db,               Bb + s * 16);
        cpa16(db + 64 * GS * 4, Bb + (size_t)64 * K + s * 16);
        cp_commit();
    }

    float acc[4][4][4];
#pragma unroll
    for (int i = 0; i < 4; i++)
#pragma unroll
        for (int j = 0; j < 4; j++)
#pragma unroll
            for (int r = 0; r < 4; r++) acc[i][j][r] = 0.f;

    for (int kt = 0; kt < NT; kt++) {
        if (kt + 1 < NT) cp_wait<1>(); else cp_wait<0>();
        __syncthreads();

        if (kt + 2 < NT) {
            int s = (kt + 2) % 3;
            unsigned da = sb + (s * GSTG + lr * GS + lc) * 4;
            unsigned db = sb + (s * GSTG + 2560 + lr * GS + lc) * 4;
            cpa16(da,               Ab + (kt + 2) * 16);
            cpa16(da + 64 * GS * 4, Ab + (size_t)64 * K + (kt + 2) * 16);
            cpa16(db,               Bb + (kt + 2) * 16);
            cpa16(db + 64 * GS * 4, Bb + (size_t)64 * K + (kt + 2) * 16);
            cp_commit();
        }

        unsigned abase = sb + ((kt % 3) * GSTG) * 4;
        unsigned bbase = abase + 2560 * 4;
#pragma unroll
        for (int kk = 0; kk < 2; kk++) {
            unsigned af[4][4];
#pragma unroll
            for (int mt = 0; mt < 4; mt++)
                ldsm4(af[mt], abase + (((wm * 64 + mt * 16 + ar) * GS) + kk * 8 + ac) * 4);
            unsigned bf[4][2];
#pragma unroll
            for (int p = 0; p < 2; p++) {
                unsigned r[4];
                ldsm4(r, bbase + (((wn * 32 + p * 16 + br) * GS) + kk * 8 + bc) * 4);
                bf[2 * p][0] = r[0]; bf[2 * p][1] = r[1];
                bf[2 * p + 1][0] = r[2]; bf[2 * p + 1][1] = r[3];
            }
#pragma unroll
            for (int mt = 0; mt < 4; mt++)
#pragma unroll
                for (int nt = 0; nt < 4; nt++)
                    mma8(acc[mt][nt], af[mt], bf[nt]);
        }
    }

#pragma unroll
    for (int mt = 0; mt < 4; mt++) {
        int r = row0 + wm * 64 + mt * 16 + g;
#pragma unroll
        for (int nt = 0; nt < 4; nt++) {
            int c = col0 + wn * 32 + nt * 8 + 2 * t;
            float b0 = bias[c], b1 = bias[c + 1];
            float v00 = acc[mt][nt][0] + b0, v01 = acc[mt][nt][1] + b1;
            float v10 = acc[mt][nt][2] + b0, v11 = acc[mt][nt][3] + b1;
            if (ROUND_OUT) {
                v00 = __uint_as_float(f2tf(v00)); v01 = __uint_as_float(f2tf(v01));
                v10 = __uint_as_float(f2tf(v10)); v11 = __uint_as_float(f2tf(v11));
            }
            *(float2*)&C[(size_t)r * N + c]       = make_float2(v00, v01);
            *(float2*)&C[(size_t)(r + 8) * N + c] = make_float2(v10, v11);
        }
    }
}

// ---------------------------------------------------------------------------
// Flash attention, tf32 MMA, cp.async pipeline. BQ=256, 8 warps (32 rows each).
// smem words: Q[256][84] | K0[64][84] | K1[64][84] | Vt[80][76] | P[256][68]
// ---------------------------------------------------------------------------
#define QSTR 84
#define VTSTR 76
#define PSTR 68
#define K0OFF (256 * QSTR)            // 21504
#define K1OFF (K0OFF + 64 * QSTR)     // 26880
#define VOFF  (K1OFF + 64 * QSTR)     // 32256
#define POFF  (VOFF + HDIM * VTSTR)   // 38336
#define ASMEM ((POFF + 256 * PSTR) * 4)  // 222976 bytes

__global__ __launch_bounds__(256)
void attn_tc(const unsigned* __restrict__ qkv, const unsigned* __restrict__ vT,
             unsigned* __restrict__ attn_out)
{
    extern __shared__ unsigned sm[];
    unsigned sb = (unsigned)__cvta_generic_to_shared(sm);

    int tid = threadIdx.x, lane = tid & 31, wid = tid >> 5;
    int g = lane >> 2, t = lane & 3;
    int q0 = blockIdx.x * 256;
    int h = blockIdx.y, b = blockIdx.z, kvh = h >> 2;
    int wr0 = wid * 32;

    int ar = lane & 15, ac = (lane >> 4) * 4;
    int br = (lane & 7) + (lane >> 4) * 8, bc = ((lane >> 3) & 1) * 4;

    const unsigned* qg = qkv + (size_t)(b * SEQ + q0) * QKV_OUT + h * HDIM;
    const unsigned* kg = qkv + (size_t)(b * SEQ) * QKV_OUT + Q_SIZE + kvh * HDIM;
    const unsigned* vtg = vT + (size_t)(b * 4 + kvh) * HDIM * SEQ;

    // prologue: Q + K(0)
    for (int i = tid * 4; i < 256 * HDIM; i += 1024) {
        int r = i / HDIM, d = i % HDIM;
        cpa16(sb + (r * QSTR + d) * 4, qg + (size_t)r * QKV_OUT + d);
    }
    for (int i = tid * 4; i < 64 * HDIM; i += 1024) {
        int r = i / HDIM, d = i % HDIM;
        cpa16(sb + (K0OFF + r * QSTR + d) * 4, kg + (size_t)r * QKV_OUT + d);
    }
    cp_commit();

    float m_i[4], l_i[4], oacc[2][10][4];
#pragma unroll
    for (int i = 0; i < 4; i++) { m_i[i] = -1e30f; l_i[i] = 0.f; }
#pragma unroll
    for (int mt = 0; mt < 2; mt++)
#pragma unroll
        for (int dn = 0; dn < 10; dn++)
#pragma unroll
            for (int r = 0; r < 4; r++) oacc[mt][dn][r] = 0.f;

    for (int kt = 0; kt < SEQ / 64; kt++) {
        cp_wait<0>();          // K(kt) + prior V complete
        __syncthreads();       // [A] also: everyone done reading old Vt

        // issue Vt(kt): rows d=0..79, cols = this kv chunk
        for (int i = tid * 4; i < HDIM * 64; i += 1024) {
            int r = i >> 6, c = i & 63;
            cpa16(sb + (VOFF + r * VTSTR + c) * 4,
                  vtg + (size_t)r * SEQ + kt * 64 + c);
        }
        cp_commit();

        unsigned kbase = sb + ((kt & 1) ? K1OFF : K0OFF) * 4;

        // S = Q . K^T
        float sacc[2][8][4];
#pragma unroll
        for (int mt = 0; mt < 2; mt++)
#pragma unroll
            for (int nt = 0; nt < 8; nt++)
#pragma unroll
                for (int r = 0; r < 4; r++) sacc[mt][nt][r] = 0.f;

#pragma unroll
        for (int kk = 0; kk < 10; kk++) {
            unsigned qa[2][4];
#pragma unroll
            for (int mt = 0; mt < 2; mt++)
                ldsm4(qa[mt], sb + (((wr0 + mt * 16 + ar) * QSTR) + kk * 8 + ac) * 4);
            unsigned kb[8][2];
#pragma unroll
            for (int p = 0; p < 4; p++) {
                unsigned r[4];
                ldsm4(r, kbase + (((p * 16 + br) * QSTR) + kk * 8 + bc) * 4);
                kb[2 * p][0] = r[0]; kb[2 * p][1] = r[1];
                kb[2 * p + 1][0] = r[2]; kb[2 * p + 1][1] = r[3];
            }
#pragma unroll
            for (int mt = 0; mt < 2; mt++)
#pragma unroll
                for (int nt = 0; nt < 8; nt++)
                    mma8(sacc[mt][nt], qa[mt], kb[nt]);
        }

        // online softmax; write P (tf32) to smem (own-warp rows only)
#pragma unroll
        for (int mt = 0; mt < 2; mt++) {
            float mx0 = -1e30f, mx1 = -1e30f;
#pragma unroll
            for (int nt = 0; nt < 8; nt++) {
                mx0 = fmaxf(mx0, fmaxf(sacc[mt][nt][0], sacc[mt][nt][1]));
                mx1 = fmaxf(mx1, fmaxf(sacc[mt][nt][2], sacc[mt][nt][3]));
            }
            mx0 = fmaxf(mx0, __shfl_xor_sync(0xffffffffu, mx0, 1));
            mx0 = fmaxf(mx0, __shfl_xor_sync(0xffffffffu, mx0, 2));
            mx1 = fmaxf(mx1, __shfl_xor_sync(0xffffffffu, mx1, 1));
            mx1 = fmaxf(mx1, __shfl_xor_sync(0xffffffffu, mx1, 2));

            int s0 = mt * 2, s1 = mt * 2 + 1;
            float mn0 = fmaxf(m_i[s0], mx0), mn1 = fmaxf(m_i[s1], mx1);
            float a0 = __expf(m_i[s0] - mn0), a1 = __expf(m_i[s1] - mn1);
            m_i[s0] = mn0; m_i[s1] = mn1;

            float rs0 = 0.f, rs1 = 0.f;
            int rb2 = wr0 + mt * 16;
#pragma unroll
            for (int nt = 0; nt < 8; nt++) {
                float p0 = __expf(sacc[mt][nt][0] - mn0);
                float p1 = __expf(sacc[mt][nt][1] - mn0);
                float p2 = __expf(sacc[mt][nt][2] - mn1);
                float p3 = __expf(sacc[mt][nt][3] - mn1);
                rs0 += p0 + p1; rs1 += p2 + p3;
                *(uint2*)&sm[POFF + (rb2 + g) * PSTR + nt * 8 + 2 * t] =
                    make_uint2(f2tf(p0), f2tf(p1));
                *(uint2*)&sm[POFF + (rb2 + g + 8) * PSTR + nt * 8 + 2 * t] =
                    make_uint2(f2tf(p2), f2tf(p3));
            }
            rs0 += __shfl_xor_sync(0xffffffffu, rs0, 1);
            rs0 += __shfl_xor_sync(0xffffffffu, rs0, 2);
            rs1 += __shfl_xor_sync(0xffffffffu, rs1, 1);
            rs1 += __shfl_xor_sync(0xffffffffu, rs1, 2);
            l_i[s0] = l_i[s0] * a0 + rs0;
            l_i[s1] = l_i[s1] * a1 + rs1;
            if (a0 != 1.f || a1 != 1.f) {
#pragma unroll
                for (int dn = 0; dn < 10; dn++) {
                    oacc[mt][dn][0] *= a0; oacc[mt][dn][1] *= a0;
                    oacc[mt][dn][2] *= a1; oacc[mt][dn][3] *= a1;
                }
            }
        }

        // issue K(kt+1); wait Vt(kt)
        if (kt + 1 < SEQ / 64) {
            unsigned kdst = sb + (((kt + 1) & 1) ? K1OFF : K0OFF) * 4;
            for (int i = tid * 4; i < 64 * HDIM; i += 1024) {
                int r = i / HDIM, d = i % HDIM;
                cpa16(kdst + (r * QSTR + d) * 4,
                      kg + (size_t)((kt + 1) * 64 + r) * QKV_OUT + d);
            }
            cp_commit();
            cp_wait<1>();
        } else {
            cp_wait<0>();
        }
        __syncthreads();       // [C] Vt visible (P is warp-private)

        // O += P . V   (V fragments via ldsm on Vt rows)
#pragma unroll
        for (int kk = 0; kk < 8; kk++) {
            unsigned pa[2][4];
#pragma unroll
            for (int mt = 0; mt < 2; mt++)
                ldsm4(pa[mt], sb + ((POFF + (wr0 + mt * 16 + ar) * PSTR) + kk * 8 + ac) * 4);
            unsigned vb[10][2];
#pragma unroll
            for (int p = 0; p < 5; p++) {
                unsigned r[4];
                ldsm4(r, sb + ((VOFF + (p * 16 + br) * VTSTR) + kk * 8 + bc) * 4);
                vb[2 * p][0] = r[0]; vb[2 * p][1] = r[1];
                vb[2 * p + 1][0] = r[2]; vb[2 * p + 1][1] = r[3];
            }
#pragma unroll
            for (int mt = 0; mt < 2; mt++)
#pragma unroll
                for (int dn = 0; dn < 10; dn++)
                    mma8(oacc[mt][dn], pa[mt], vb[dn]);
        }
    }

    // normalize + write tf32 bits (feeds O-proj cp.async)
#pragma unroll
    for (int mt = 0; mt < 2; mt++) {
        float inv0 = 1.f / l_i[mt * 2], inv1 = 1.f / l_i[mt * 2 + 1];
        int r = q0 + wr0 + mt * 16 + g;
#pragma unroll
        for (int dn = 0; dn < 10; dn++) {
            int c = h * HDIM + dn * 8 + 2 * t;
            *(uint2*)&attn_out[(size_t)(b * SEQ + r) * Q_SIZE + c] =
                make_uint2(f2tf(oacc[mt][dn][0] * inv0), f2tf(oacc[mt][dn][1] * inv0));
            *(uint2*)&attn_out[(size_t)(b * SEQ + r + 8) * Q_SIZE + c] =
                make_uint2(f2tf(oacc[mt][dn][2] * inv1), f2tf(oacc[mt][dn][3] * inv1));
        }
    }
}

// ---------------------------------------------------------------------------
extern "C" void kernel_launch(void* const* d_in, const int* in_sizes, int n_in,
                              void* d_out, int out_size)
{
    const float* hidden  = (const float*)d_in[0];
    const float* scaling = (const float*)d_in[1];
    const float* qkv_w   = (const float*)d_in[2];
    const float* qkv_b   = (const float*)d_in[3];
    const float* o_w     = (const float*)d_in[4];
    const float* o_b     = (const float*)d_in[5];
    float* out = (float*)d_out;

    unsigned *hidc, *wqkv, *wo, *qkvb, *vtb, *attnb;
    float *bqkv;
    cudaGetSymbolAddress((void**)&hidc,  g_hidc);
    cudaGetSymbolAddress((void**)&wqkv,  g_wqkv);
    cudaGetSymbolAddress((void**)&bqkv,  g_bqkv);
    cudaGetSymbolAddress((void**)&wo,    g_wo);
    cudaGetSymbolAddress((void**)&qkvb,  g_qkv);
    cudaGetSymbolAddress((void**)&vtb,   g_vT);
    cudaGetSymbolAddress((void**)&attnb, g_attn);

    static bool attr_set = false;
    if (!attr_set) {
        cudaFuncSetAttribute(attn_tc,
                             cudaFuncAttributeMaxDynamicSharedMemorySize, ASMEM);
        cudaFuncSetAttribute(gemm_tc<true>,
                             cudaFuncAttributeMaxDynamicSharedMemorySize, GSMEM);
        cudaFuncSetAttribute(gemm_tc<false>,
                             cudaFuncAttributeMaxDynamicSharedMemorySize, GSMEM);
        attr_set = true;
    }

    // 0) prep
    k_conv<<<2048, 256>>>(hidden, hidc, ROWS * HIDDEN / 4);
    k_conv_wqkv<<<1200, 512>>>(qkv_w, qkv_b, scaling);
    k_conv<<<800, 512>>>(o_w, wo, HIDDEN * Q_SIZE / 4);

    // 1) QKV projection -> g_qkv (tf32-rounded)
    {
        dim3 grid(QKV_OUT / 128, ROWS / 128);
        gemm_tc<true><<<grid, 256, GSMEM>>>(hidc, wqkv, bqkv, (float*)qkvb,
                                            ROWS, QKV_OUT, HIDDEN);
    }
    // 1b) transpose V -> g_vT
    {
        dim3 grid(SEQ / 32, 3, BATCH * 4);
        k_vT<<<grid, dim3(32, 8)>>>(qkvb, vtb);
    }
    // 2) attention -> g_attn (tf32-rounded)
    {
        dim3 grid(SEQ / 256, NUM_H, BATCH);
        attn_tc<<<grid, 256, ASMEM>>>(qkvb, vtb, attnb);
    }
    // 3) output projection -> out (fp32)
    {
        dim3 grid(HIDDEN / 128, ROWS / 128);
        gemm_tc<false><<<grid, 256, GSMEM>>>(attnb, wo, o_b, out,
                                             ROWS, HIDDEN, Q_SIZE);
    }
}